// round 1
// baseline (speedup 1.0000x reference)
#include <cuda_runtime.h>

// InverseHaar: input (B=16, C=256, H=128, W=128) fp32, C = 4 bands x G=64 groups.
// Output (B=16, G=64, 2H=256, 2W=256) fp32.
// out[b,g,2h+0, 2w+0] = (a+h+v+d)/4   (tl)
// out[b,g,2h+0, 2w+1] = (a-h+v-d)/4   (tr)
// out[b,g,2h+1, 2w+0] = (a+h-v-d)/4   (bl)
// out[b,g,2h+1, 2w+1] = (a-h-v+d)/4   (br)
// where a=x[b,0,g,h,w], h=x[b,1,g,h,w], v=x[b,2,g,h,w], d=x[b,3,g,h,w].

#define B_  16
#define G_  64
#define H_  128
#define W_  128
#define HW_ (H_ * W_)              // 16384
#define BAND_STRIDE_ (G_ * HW_)    // 1048576 elements between bands (same b)
#define W4_ (W_ / 4)               // 32 float4 per input row
#define OW_ (2 * W_)               // 256 output width
#define OH_ (2 * H_)               // 256 output height

__global__ void __launch_bounds__(256) inverse_haar_kernel(
    const float4* __restrict__ in,   // viewed as float4
    float4* __restrict__ out)        // viewed as float4
{
    // One thread per (b, g, h, w4) with w4 covering 4 consecutive w.
    int idx = blockIdx.x * blockDim.x + threadIdx.x;
    // total = B * G * H * W4 = 16*64*128*32 = 4194304; launched exactly.

    int w4 = idx & (W4_ - 1);
    int t  = idx >> 5;            // / 32
    int h  = t & (H_ - 1);
    t >>= 7;                      // / 128
    int g  = t & (G_ - 1);
    int b  = t >> 6;              // / 64

    // Input base (in float4 units): ((b*4 + 0)*G + g)*HW + h*W + w4*4, all /4
    long base = ((long)(b * 4) * G_ + g) * (HW_ / 4) + (long)h * (W_ / 4) + w4;
    const long S = BAND_STRIDE_ / 4;   // band stride in float4 units

    float4 va = in[base];
    float4 vh = in[base + S];
    float4 vv = in[base + 2 * S];
    float4 vd = in[base + 3 * S];

    const float Q = 0.25f;

    // Per-lane Haar synthesis
    float tl0 = (va.x + vh.x + vv.x + vd.x) * Q;
    float tr0 = (va.x - vh.x + vv.x - vd.x) * Q;
    float bl0 = (va.x + vh.x - vv.x - vd.x) * Q;
    float br0 = (va.x - vh.x - vv.x + vd.x) * Q;

    float tl1 = (va.y + vh.y + vv.y + vd.y) * Q;
    float tr1 = (va.y - vh.y + vv.y - vd.y) * Q;
    float bl1 = (va.y + vh.y - vv.y - vd.y) * Q;
    float br1 = (va.y - vh.y - vv.y + vd.y) * Q;

    float tl2 = (va.z + vh.z + vv.z + vd.z) * Q;
    float tr2 = (va.z - vh.z + vv.z - vd.z) * Q;
    float bl2 = (va.z + vh.z - vv.z - vd.z) * Q;
    float br2 = (va.z - vh.z - vv.z + vd.z) * Q;

    float tl3 = (va.w + vh.w + vv.w + vd.w) * Q;
    float tr3 = (va.w - vh.w + vv.w - vd.w) * Q;
    float bl3 = (va.w + vh.w - vv.w - vd.w) * Q;
    float br3 = (va.w - vh.w - vv.w + vd.w) * Q;

    // Output: row-major (B, G, OH, OW). This thread writes 8 floats in row 2h
    // starting at column 8*w4, and 8 floats in row 2h+1. As float4: 2 stores/row.
    long orow0 = (((long)(b * G_ + g) * OH_) + 2 * h) * (OW_ / 4) + w4 * 2;
    long orow1 = orow0 + (OW_ / 4);

    out[orow0]     = make_float4(tl0, tr0, tl1, tr1);
    out[orow0 + 1] = make_float4(tl2, tr2, tl3, tr3);
    out[orow1]     = make_float4(bl0, br0, bl1, br1);
    out[orow1 + 1] = make_float4(bl2, br2, bl3, br3);
}

extern "C" void kernel_launch(void* const* d_in, const int* in_sizes, int n_in,
                              void* d_out, int out_size)
{
    const float4* in = (const float4*)d_in[0];
    float4* out = (float4*)d_out;

    int total_threads = B_ * G_ * H_ * W4_;   // 4,194,304
    int block = 256;
    int grid = total_threads / block;         // 16384
    inverse_haar_kernel<<<grid, block>>>(in, out);
}

// round 2
// speedup vs baseline: 1.0305x; 1.0305x over previous
#include <cuda_runtime.h>

// InverseHaar: input (B=16, C=256, H=128, W=128) fp32, C = 4 bands x G=64 groups.
// Output (B=16, G=64, 2H=256, 2W=256) fp32.
//
// Warp-contiguous-store layout:
//   lane l of a warp owns input w in {2l, 2l+1} (first half-row) and
//   {64+2l, 64+2l+1} (second half-row) for one (b,g,h).
//   It writes output float4 (16B) at row positions l and l+32 of both output
//   rows 2h and 2h+1 -> every STG.128 is a contiguous 512B warp transaction.

#define B_  16
#define G_  64
#define H_  128
#define W_  128
#define HW_ (H_ * W_)              // 16384
#define BAND_STRIDE_ (G_ * HW_)    // 1048576 floats between bands (same b)
#define OW_ (2 * W_)               // 256 output width
#define OH_ (2 * H_)               // 256 output height

__global__ void __launch_bounds__(256) inverse_haar_kernel(
    const float2* __restrict__ in,   // viewed as float2
    float4* __restrict__ out)        // viewed as float4
{
    int idx = blockIdx.x * blockDim.x + threadIdx.x;
    // total threads = B*G*H*32 = 4,194,304 (32 lanes cover one full input row)

    int l  = idx & 31;            // lane-role within a row
    int t  = idx >> 5;
    int h  = t & (H_ - 1);
    t >>= 7;
    int g  = t & (G_ - 1);
    int b  = t >> 6;

    // Input base in float2 units: band a, (b,g,h) row, element pair l (w=2l,2l+1)
    long base = ((long)(b * 4) * G_ + g) * (HW_ / 2) + (long)h * (W_ / 2) + l;
    const long S = BAND_STRIDE_ / 2;   // band stride in float2 units
    const int  HALF = 32;              // second half-row offset in float2 units (w=64)

    // 8 independent streaming loads -> MLP=8
    float2 a0 = __ldcs(&in[base]);
    float2 a1 = __ldcs(&in[base + HALF]);
    float2 h0 = __ldcs(&in[base + S]);
    float2 h1 = __ldcs(&in[base + S + HALF]);
    float2 v0 = __ldcs(&in[base + 2 * S]);
    float2 v1 = __ldcs(&in[base + 2 * S + HALF]);
    float2 d0 = __ldcs(&in[base + 3 * S]);
    float2 d1 = __ldcs(&in[base + 3 * S + HALF]);

    const float Q = 0.25f;

    // group 0: w = 2l (x), 2l+1 (y)
    float tl0x = (a0.x + h0.x + v0.x + d0.x) * Q;
    float tr0x = (a0.x - h0.x + v0.x - d0.x) * Q;
    float bl0x = (a0.x + h0.x - v0.x - d0.x) * Q;
    float br0x = (a0.x - h0.x - v0.x + d0.x) * Q;

    float tl0y = (a0.y + h0.y + v0.y + d0.y) * Q;
    float tr0y = (a0.y - h0.y + v0.y - d0.y) * Q;
    float bl0y = (a0.y + h0.y - v0.y - d0.y) * Q;
    float br0y = (a0.y - h0.y - v0.y + d0.y) * Q;

    // group 1: w = 64+2l (x), 64+2l+1 (y)
    float tl1x = (a1.x + h1.x + v1.x + d1.x) * Q;
    float tr1x = (a1.x - h1.x + v1.x - d1.x) * Q;
    float bl1x = (a1.x + h1.x - v1.x - d1.x) * Q;
    float br1x = (a1.x - h1.x - v1.x + d1.x) * Q;

    float tl1y = (a1.y + h1.y + v1.y + d1.y) * Q;
    float tr1y = (a1.y - h1.y + v1.y - d1.y) * Q;
    float bl1y = (a1.y + h1.y - v1.y - d1.y) * Q;
    float br1y = (a1.y - h1.y - v1.y + d1.y) * Q;

    // Output row bases (float4 units). Row has OW_/4 = 64 float4.
    long orow0 = (((long)(b * G_ + g) * OH_) + 2 * h) * (OW_ / 4) + l;
    long orow1 = orow0 + (OW_ / 4);

    // Each store: lanes 0..31 hit consecutive 16B slots -> contiguous 512B.
    __stcs(&out[orow0],      make_float4(tl0x, tr0x, tl0y, tr0y));
    __stcs(&out[orow0 + 32], make_float4(tl1x, tr1x, tl1y, tr1y));
    __stcs(&out[orow1],      make_float4(bl0x, br0x, bl0y, br0y));
    __stcs(&out[orow1 + 32], make_float4(bl1x, br1x, bl1y, br1y));
}

extern "C" void kernel_launch(void* const* d_in, const int* in_sizes, int n_in,
                              void* d_out, int out_size)
{
    const float2* in = (const float2*)d_in[0];
    float4* out = (float4*)d_out;

    int total_threads = B_ * G_ * H_ * 32;   // 4,194,304
    int block = 256;
    int grid = total_threads / block;         // 16384
    inverse_haar_kernel<<<grid, block>>>(in, out);
}

// round 3
// speedup vs baseline: 1.0369x; 1.0063x over previous
#include <cuda_runtime.h>

// InverseHaar: input (B=16, C=256, H=128, W=128) fp32, C = 4 bands x G=64 groups.
// Output (B=16, G=64, 2H=256, 2W=256) fp32.
//
// One thread per (b, g, h, half, l): lane l handles input w in {2l, 2l+1} of
// the `half`-th half-row. 4 front-batched loads (MLP_p1=4), 2 contiguous
// 512B-per-warp float4 stores.

#define B_  16
#define G_  64
#define H_  128
#define W_  128
#define HW_ (H_ * W_)              // 16384
#define BAND_STRIDE_ (G_ * HW_)    // 1048576 floats between bands (same b)
#define OW_ (2 * W_)               // 256 output width
#define OH_ (2 * H_)               // 256 output height

__global__ void __launch_bounds__(256) inverse_haar_kernel(
    const float2* __restrict__ in,   // viewed as float2
    float4* __restrict__ out)        // viewed as float4
{
    int idx = blockIdx.x * blockDim.x + threadIdx.x;
    // total threads = B*G*H*2*32 = 8,388,608

    int l    = idx & 31;          // lane: w pair within half-row
    int t    = idx >> 5;
    int half = t & 1;             // which half of the input row (w<64 or w>=64)
    t >>= 1;
    int h    = t & (H_ - 1);
    t >>= 7;
    int g    = t & (G_ - 1);
    int b    = t >> 6;

    // Input base in float2 units: band a, (b,g,h) row, pair index half*32 + l
    long base = ((long)(b * 4) * G_ + g) * (HW_ / 2) + (long)h * (W_ / 2)
              + half * 32 + l;
    const long S = BAND_STRIDE_ / 2;   // band stride in float2 units

    // 4 independent streaming loads (MLP_p1 = 4)
    float2 va = __ldcs(&in[base]);
    float2 vh = __ldcs(&in[base + S]);
    float2 vv = __ldcs(&in[base + 2 * S]);
    float2 vd = __ldcs(&in[base + 3 * S]);

    const float Q = 0.25f;

    float tlx = (va.x + vh.x + vv.x + vd.x) * Q;
    float trx = (va.x - vh.x + vv.x - vd.x) * Q;
    float blx = (va.x + vh.x - vv.x - vd.x) * Q;
    float brx = (va.x - vh.x - vv.x + vd.x) * Q;

    float tly = (va.y + vh.y + vv.y + vd.y) * Q;
    float try_ = (va.y - vh.y + vv.y - vd.y) * Q;
    float bly = (va.y + vh.y - vv.y - vd.y) * Q;
    float bry = (va.y - vh.y - vv.y + vd.y) * Q;

    // Output row bases (float4 units). Row has OW_/4 = 64 float4.
    // This thread's float4 slot within the row: half*32 + l.
    long orow0 = (((long)(b * G_ + g) * OH_) + 2 * h) * (OW_ / 4) + half * 32 + l;
    long orow1 = orow0 + (OW_ / 4);

    // Each store: lanes 0..31 hit consecutive 16B slots -> contiguous 512B.
    __stcs(&out[orow0], make_float4(tlx, trx, tly, try_));
    __stcs(&out[orow1], make_float4(blx, brx, bly, bry));
}

extern "C" void kernel_launch(void* const* d_in, const int* in_sizes, int n_in,
                              void* d_out, int out_size)
{
    const float2* in = (const float2*)d_in[0];
    float4* out = (float4*)d_out;

    int total_threads = B_ * G_ * H_ * 2 * 32;   // 8,388,608
    int block = 256;
    int grid = total_threads / block;            // 32768
    inverse_haar_kernel<<<grid, block>>>(in, out);
}